// round 9
// baseline (speedup 1.0000x reference)
#include <cuda_runtime.h>
#include <cuda_fp16.h>
#include <stdint.h>

#define C_DIM 16
#define G_DIM 8192
#define S_DIM 8
#define L_DIM 3
#define B_DIM 32
#define SL    (S_DIM * L_DIM)   // 24

#define G_PER_BLOCK 32
#define N_TILES     (C_DIM * (G_DIM / G_PER_BLOCK))   // 4096
#define GRID_PERSIST (148 * 8)                         // one resident wave

// xt in fp16: row g = 32 halves = 64B, aligned. Working set 512KB.
__device__ __align__(128) __half2 g_xh[G_DIM * (B_DIM / 2)];
__device__ int g_idx_is64;

// ---------------------------------------------------------------------------
// Kernel 1: transpose x (B,G) f32 -> g_xh (G, B/2) half2, no smem.
// thread = (g, octet q): loads x[8q+k][g] k=0..7, writes one 16B quarter-row.
// 128 blocks x 256 threads. Also detects idx width in (0,0).
// ---------------------------------------------------------------------------
__global__ __launch_bounds__(256)
void transpose_x_kernel(const float* __restrict__ x,
                        const int* __restrict__ Iw) {
    if (blockIdx.x == 0 && threadIdx.x == 0) {
        int is64 = 1;
#pragma unroll
        for (int k = 0; k < 16; k++) {
            if (Iw[2 * k + 1] != 0) is64 = 0;
        }
        g_idx_is64 = is64;
    }

    const int t = blockIdx.x * 256 + threadIdx.x;
    const int g = t >> 2;
    const int q = t & 3;          // b = 8q .. 8q+7

    unsigned w[4];
#pragma unroll
    for (int k = 0; k < 4; k++) {
        float f0 = x[(8 * q + 2 * k    ) * G_DIM + g];
        float f1 = x[(8 * q + 2 * k + 1) * G_DIM + g];
        __half2 h = __floats2half2_rn(f0, f1);
        w[k] = *(unsigned*)&h;
    }

    uint4* dst = (uint4*)&g_xh[g * (B_DIM / 2) + q * 4];
    *dst = make_uint4(w[0], w[1], w[2], w[3]);
}

// Extract byte offset (idx*64) for index slot k (0..23) from 12 packed words.
// Stored value is (idx<<3) in a u16; lo half in bits[0:16), hi in [16:32).
__device__ __forceinline__ int idx_off(const unsigned* uw, int k) {
    unsigned w = uw[k >> 1];
    return (k & 1) ? (int)((w >> 13) & 0x7FFF8u)
                   : (int)((w << 3) & 0x7FFF8u);
}

// ---------------------------------------------------------------------------
// Kernel 2 (persistent): 1184 blocks = one resident wave; grid-stride over
// 4096 tiles of (c, 32 g). Per tile: warp handles 4 g (lane>>3 = sub-g,
// lane&7 = 8B octet; LDG.64 gathers). u16-packed indices -> 3 LDS.128 -> regs.
// fp16 pair-accumulate, fp32 master accumulators, float4 epilogue.
// ---------------------------------------------------------------------------
__global__ __launch_bounds__(256, 8)
void clause_body_kernel(const void* __restrict__ Iraw,
                        float* __restrict__ out) {
    __shared__ unsigned short sIdx[G_PER_BLOCK * SL];   // 1.5 KB
    __shared__ float tile[B_DIM][33];                   // 4.2 KB

    const int tid  = threadIdx.x;
    const int warp = tid >> 5;
    const int lane = tid & 31;
    const int gl   = warp * 4 + (lane >> 3);   // local g (0..31)
    const int oct  = lane & 7;                 // 8B octet -> b = 4*oct..4*oct+3
    const char* xb = (const char*)g_xh + oct * 8;

    const int is64 = g_idx_is64;

    // epilogue mapping (hoisted)
    const int eb = tid >> 3;          // 0..31
    const int eq = (tid & 7) * 4;     // 0..28

    for (int tileId = blockIdx.x; tileId < N_TILES; tileId += GRID_PERSIST) {
        const int c      = tileId >> 8;           // 256 tiles of 32 g per c
        const int g_base = (tileId & 255) << 5;   // *32

        // Stage 768 indices as u16 = (idx & 8191) << 3. Flat e = g*24+k.
        const long long base = ((long long)(c * G_DIM + g_base)) * SL;
        if (is64) {
            const long long* Ip = (const long long*)Iraw + base;
#pragma unroll
            for (int k = 0; k < 3; k++) {
                int e = tid + k * 256;
                sIdx[e] = (unsigned short)((((int)Ip[e]) & (G_DIM - 1)) << 3);
            }
        } else {
            const int* Ip = (const int*)Iraw + base;
#pragma unroll
            for (int k = 0; k < 3; k++) {
                int e = tid + k * 256;
                sIdx[e] = (unsigned short)((Ip[e] & (G_DIM - 1)) << 3);
            }
        }
        __syncthreads();   // sync1: staging done; also orders prev epilogue
                           // reads of `tile` before this tile's writes.

        // Pull 24 packed indices for this g: 3 x LDS.128, 12 regs.
        unsigned uw[12];
        {
            const uint4* myI = (const uint4*)&sIdx[gl * SL];
            uint4 w0 = myI[0], w1 = myI[1], w2 = myI[2];
            uw[0] = w0.x; uw[1] = w0.y; uw[2]  = w0.z; uw[3]  = w0.w;
            uw[4] = w1.x; uw[5] = w1.y; uw[6]  = w1.z; uw[7]  = w1.w;
            uw[8] = w2.x; uw[9] = w2.y; uw[10] = w2.z; uw[11] = w2.w;
        }

        float a0 = 0.f, a1 = 0.f, a2 = 0.f, a3 = 0.f;
#pragma unroll
        for (int j = 0; j < 4; j++) {           // s = 2j, 2j+1
            int k = 6 * j;
            uint2 r0 = *(const uint2*)(xb + idx_off(uw, k + 0));
            uint2 r1 = *(const uint2*)(xb + idx_off(uw, k + 1));
            uint2 r2 = *(const uint2*)(xb + idx_off(uw, k + 2));
            uint2 r3 = *(const uint2*)(xb + idx_off(uw, k + 3));
            uint2 r4 = *(const uint2*)(xb + idx_off(uw, k + 4));
            uint2 r5 = *(const uint2*)(xb + idx_off(uw, k + 5));

            __half2 pa0 = __hmul2(__hmul2(*(__half2*)&r0.x, *(__half2*)&r1.x), *(__half2*)&r2.x);
            __half2 pb0 = __hmul2(__hmul2(*(__half2*)&r0.y, *(__half2*)&r1.y), *(__half2*)&r2.y);
            __half2 pa1 = __hmul2(__hmul2(*(__half2*)&r3.x, *(__half2*)&r4.x), *(__half2*)&r5.x);
            __half2 pb1 = __hmul2(__hmul2(*(__half2*)&r3.y, *(__half2*)&r4.y), *(__half2*)&r5.y);

            __half2 qa = __hadd2(pa0, pa1);     // pair-sum in fp16
            __half2 qb = __hadd2(pb0, pb1);
            float2 fa = __half22float2(qa);
            float2 fb = __half22float2(qb);
            a0 += fa.x; a1 += fa.y;
            a2 += fb.x; a3 += fb.y;
        }

        // tile[b][gl], bank = 4*oct + gl + i mod 32 -> conflict-free.
        tile[4 * oct + 0][gl] = a0;
        tile[4 * oct + 1][gl] = a1;
        tile[4 * oct + 2][gl] = a2;
        tile[4 * oct + 3][gl] = a3;
        __syncthreads();   // sync2: compute done (sIdx free), tile complete.

        // Writeout: thread -> (b, 4 consecutive g), one STG.128.
        float4 v = make_float4(tile[eb][eq + 0], tile[eb][eq + 1],
                               tile[eb][eq + 2], tile[eb][eq + 3]);
        *(float4*)&out[((long long)c * B_DIM + eb) * G_DIM + g_base + eq] = v;
    }
}

extern "C" void kernel_launch(void* const* d_in, const int* in_sizes, int n_in,
                              void* d_out, int out_size) {
    const float* x = nullptr;
    const void*  I = nullptr;
    for (int i = 0; i < n_in; i++) {
        if (in_sizes[i] == B_DIM * G_DIM)            x = (const float*)d_in[i];
        else if (in_sizes[i] == C_DIM * G_DIM * SL)  I = d_in[i];
    }
    float* out = (float*)d_out;

    transpose_x_kernel<<<(G_DIM * 4) / 256, 256>>>(x, (const int*)I);

    clause_body_kernel<<<GRID_PERSIST, 256>>>(I, out);
}

// round 10
// speedup vs baseline: 1.0845x; 1.0845x over previous
#include <cuda_runtime.h>
#include <cuda_fp16.h>
#include <stdint.h>

#define C_DIM 16
#define G_DIM 8192
#define S_DIM 8
#define L_DIM 3
#define B_DIM 32
#define SL    (S_DIM * L_DIM)   // 24

#define G_PER_BLOCK 32

// xt in fp16: row g = 32 halves = 64B, aligned. Working set 512KB.
__device__ __align__(128) __half2 g_xh[G_DIM * (B_DIM / 2)];

// ---------------------------------------------------------------------------
// Kernel 1: transpose x (B,G) f32 -> g_xh (G, B/2) half2, no smem.
// thread = (g, octet q): loads x[8q+k][g] k=0..7, writes one 16B quarter-row.
// 128 blocks x 256 threads.
// ---------------------------------------------------------------------------
__global__ __launch_bounds__(256)
void transpose_x_kernel(const float* __restrict__ x) {
    const int t = blockIdx.x * 256 + threadIdx.x;
    const int g = t >> 2;
    const int q = t & 3;          // b = 8q .. 8q+7

    unsigned w[4];
#pragma unroll
    for (int k = 0; k < 4; k++) {
        float f0 = x[(8 * q + 2 * k    ) * G_DIM + g];
        float f1 = x[(8 * q + 2 * k + 1) * G_DIM + g];
        __half2 h = __floats2half2_rn(f0, f1);
        w[k] = *(unsigned*)&h;
    }

    uint4* dst = (uint4*)&g_xh[g * (B_DIM / 2) + q * 4];
    *dst = make_uint4(w[0], w[1], w[2], w[3]);
}

// Extract byte offset (idx*64) for index slot k (0..23) from 12 packed words.
// Stored value is (idx<<3) in a u16; lo half in bits[0:16), hi in [16:32).
__device__ __forceinline__ int idx_off(const unsigned* uw, int k) {
    unsigned w = uw[k >> 1];
    return (k & 1) ? (int)((w >> 13) & 0x7FFF8u)
                   : (int)((w << 3) & 0x7FFF8u);
}

// ---------------------------------------------------------------------------
// Kernel 2: block = 256 threads = 8 warps = 32 g. Warp handles 4 g
// (lane>>3 = sub-g, lane&7 = 8B octet of the 64B xt row; LDG.64 gathers).
// Launched with PDL: index staging (doesn't touch g_xh) overlaps the
// transpose kernel; cudaGridDependencySynchronize() guards the gathers.
// idx width detected in-kernel via one ballot (I's head is L1-broadcast).
// Grid: C * G/32 = 4096 blocks, 8 blocks/SM.
// ---------------------------------------------------------------------------
__global__ __launch_bounds__(256, 8)
void clause_body_kernel(const void* __restrict__ Iraw,
                        float* __restrict__ out) {
    __shared__ unsigned short sIdx[G_PER_BLOCK * SL];   // 1.5 KB
    __shared__ float tile[B_DIM][33];                   // 4.2 KB

    const int tid    = threadIdx.x;
    const int lane   = tid & 31;
    const int c      = blockIdx.x >> 8;           // 256 tiles of 32 g per c
    const int g_base = (blockIdx.x & 255) << 5;   // *32

    // Detect int64 vs int32 from I's first 16 high words (hot in L1/L2).
    int hi = 0;
    if (lane < 16) hi = ((const int*)Iraw)[2 * lane + 1];
    const bool is64 = (__ballot_sync(0xffffffffu, hi != 0) == 0u);

    // Stage 768 indices as u16 = (idx & 8191) << 3. Flat layout e = g*24+k.
    const long long base = ((long long)(c * G_DIM + g_base)) * SL;
    if (is64) {
        const long long* Ip = (const long long*)Iraw + base;
#pragma unroll
        for (int k = 0; k < 3; k++) {
            int e = tid + k * 256;
            sIdx[e] = (unsigned short)((((int)Ip[e]) & (G_DIM - 1)) << 3);
        }
    } else {
        const int* Ip = (const int*)Iraw + base;
#pragma unroll
        for (int k = 0; k < 3; k++) {
            int e = tid + k * 256;
            sIdx[e] = (unsigned short)((Ip[e] & (G_DIM - 1)) << 3);
        }
    }
    __syncthreads();

    const int warp = tid >> 5;
    const int gl   = warp * 4 + (lane >> 3);   // local g (0..31)
    const int oct  = lane & 7;                 // 8B octet -> b = 4*oct..4*oct+3

    const char* xb = (const char*)g_xh + oct * 8;

    // Pull all 24 packed indices for this g: 3 x LDS.128 (48B), 12 regs.
    unsigned uw[12];
    {
        const uint4* myI = (const uint4*)&sIdx[gl * SL];
        uint4 w0 = myI[0], w1 = myI[1], w2 = myI[2];
        uw[0] = w0.x; uw[1] = w0.y; uw[2]  = w0.z; uw[3]  = w0.w;
        uw[4] = w1.x; uw[5] = w1.y; uw[6]  = w1.z; uw[7]  = w1.w;
        uw[8] = w2.x; uw[9] = w2.y; uw[10] = w2.z; uw[11] = w2.w;
    }

    // PDL: g_xh must be complete before the first gather.
    cudaGridDependencySynchronize();

    float a0 = 0.f, a1 = 0.f, a2 = 0.f, a3 = 0.f;
#pragma unroll
    for (int j = 0; j < 4; j++) {           // s = 2j, 2j+1
        int k = 6 * j;
        uint2 r0 = *(const uint2*)(xb + idx_off(uw, k + 0));
        uint2 r1 = *(const uint2*)(xb + idx_off(uw, k + 1));
        uint2 r2 = *(const uint2*)(xb + idx_off(uw, k + 2));
        uint2 r3 = *(const uint2*)(xb + idx_off(uw, k + 3));
        uint2 r4 = *(const uint2*)(xb + idx_off(uw, k + 4));
        uint2 r5 = *(const uint2*)(xb + idx_off(uw, k + 5));

        __half2 pa0 = __hmul2(__hmul2(*(__half2*)&r0.x, *(__half2*)&r1.x), *(__half2*)&r2.x);
        __half2 pb0 = __hmul2(__hmul2(*(__half2*)&r0.y, *(__half2*)&r1.y), *(__half2*)&r2.y);
        __half2 pa1 = __hmul2(__hmul2(*(__half2*)&r3.x, *(__half2*)&r4.x), *(__half2*)&r5.x);
        __half2 pb1 = __hmul2(__hmul2(*(__half2*)&r3.y, *(__half2*)&r4.y), *(__half2*)&r5.y);

        __half2 qa = __hadd2(pa0, pa1);     // pair-sum in fp16
        __half2 qb = __hadd2(pb0, pb1);
        float2 fa = __half22float2(qa);
        float2 fb = __half22float2(qb);
        a0 += fa.x; a1 += fa.y;
        a2 += fb.x; a3 += fb.y;
    }

    // Thread holds b = 4*oct .. 4*oct+3 for g = g_base+gl. tile[b][gl]:
    // bank = (4*oct+i)*33 + gl mod 32 = 4*oct + gl + i -> conflict-free.
    tile[4 * oct + 0][gl] = a0;
    tile[4 * oct + 1][gl] = a1;
    tile[4 * oct + 2][gl] = a2;
    tile[4 * oct + 3][gl] = a3;
    __syncthreads();

    // Single-pass writeout: thread -> (b, 4 consecutive g), one STG.128.
    {
        int b  = tid >> 3;          // 0..31
        int q4 = (tid & 7) * 4;     // 0..28
        float4 v = make_float4(tile[b][q4 + 0], tile[b][q4 + 1],
                               tile[b][q4 + 2], tile[b][q4 + 3]);
        *(float4*)&out[((long long)c * B_DIM + b) * G_DIM + g_base + q4] = v;
    }
}

extern "C" void kernel_launch(void* const* d_in, const int* in_sizes, int n_in,
                              void* d_out, int out_size) {
    const float* x = nullptr;
    const void*  I = nullptr;
    for (int i = 0; i < n_in; i++) {
        if (in_sizes[i] == B_DIM * G_DIM)            x = (const float*)d_in[i];
        else if (in_sizes[i] == C_DIM * G_DIM * SL)  I = d_in[i];
    }
    float* out = (float*)d_out;

    transpose_x_kernel<<<(G_DIM * 4) / 256, 256>>>(x);

    // Clause kernel with programmatic dependent launch: overlaps its index
    // staging with the transpose; gathers are guarded by
    // cudaGridDependencySynchronize() inside the kernel.
    cudaLaunchConfig_t cfg = {};
    cfg.gridDim  = dim3(C_DIM * (G_DIM / G_PER_BLOCK));
    cfg.blockDim = dim3(256);
    cfg.dynamicSmemBytes = 0;
    cfg.stream = 0;
    cudaLaunchAttribute attrs[1];
    attrs[0].id = cudaLaunchAttributeProgrammaticStreamSerialization;
    attrs[0].val.programmaticStreamSerializationAllowed = 1;
    cfg.attrs = attrs;
    cfg.numAttrs = 1;
    cudaLaunchKernelEx(&cfg, clause_body_kernel, I, out);
}